// round 1
// baseline (speedup 1.0000x reference)
#include <cuda_runtime.h>
#include <cuda_bf16.h>
#include <stdint.h>

// Problem dims (from reference): T=4096 tokens, IC=OC=4096, N_OUT=204.
// We derive dims at runtime from in_sizes but cap scratch at 4096x4096.
#define MAX_OC 4096
#define MAX_IC 4096

// Scratch: quantized weight, per-row mean and scale.
__device__ float g_wq[(size_t)MAX_OC * MAX_IC];
__device__ float g_mean[MAX_OC];
__device__ float g_scale[MAX_OC];

// ---------------------------------------------------------------------------
// Kernel 1: per-output-row mean and mean-abs-deviation (scale).
// One block per row, 256 threads.
// ---------------------------------------------------------------------------
__global__ void rowstats_kernel(const float* __restrict__ w, int IC) {
    int o = blockIdx.x;
    const float* row = w + (size_t)o * IC;
    __shared__ float red[256];
    int tid = threadIdx.x;

    float s = 0.f;
    for (int i = tid; i < IC; i += 256) s += row[i];
    red[tid] = s;
    __syncthreads();
    #pragma unroll
    for (int off = 128; off > 0; off >>= 1) {
        if (tid < off) red[tid] += red[tid + off];
        __syncthreads();
    }
    float mean = red[0] / (float)IC;
    __syncthreads();

    float s2 = 0.f;
    for (int i = tid; i < IC; i += 256) s2 += fabsf(row[i] - mean);
    red[tid] = s2;
    __syncthreads();
    #pragma unroll
    for (int off = 128; off > 0; off >>= 1) {
        if (tid < off) red[tid] += red[tid + off];
        __syncthreads();
    }
    if (tid == 0) {
        g_mean[o]  = mean;
        g_scale[o] = red[0] / (float)IC;
    }
}

// ---------------------------------------------------------------------------
// Kernel 2: wq[o][i] = sign(w[o][i] - mean[o]) * scale[o]   (sign(0)=0)
// Vectorized float4 grid-stride.
// ---------------------------------------------------------------------------
__global__ void quantize_kernel(const float* __restrict__ w, int OC, int IC) {
    size_t n4 = (size_t)OC * IC / 4;
    const float4* w4 = reinterpret_cast<const float4*>(w);
    float4* q4 = reinterpret_cast<float4*>(g_wq);
    int ic4 = IC / 4;
    for (size_t idx = (size_t)blockIdx.x * blockDim.x + threadIdx.x; idx < n4;
         idx += (size_t)gridDim.x * blockDim.x) {
        int o = (int)(idx / ic4);
        float mean = g_mean[o];
        float scale = g_scale[o];
        float4 v = w4[idx];
        float4 r;
        float a;
        a = v.x - mean; r.x = (a > 0.f) ? scale : ((a < 0.f) ? -scale : 0.f);
        a = v.y - mean; r.y = (a > 0.f) ? scale : ((a < 0.f) ? -scale : 0.f);
        a = v.z - mean; r.z = (a > 0.f) ? scale : ((a < 0.f) ? -scale : 0.f);
        a = v.w - mean; r.w = (a > 0.f) ? scale : ((a < 0.f) ? -scale : 0.f);
        q4[idx] = r;
    }
}

// ---------------------------------------------------------------------------
// Kernel 3: overwrite outlier columns: wq[:, idx[j]] = ow[:, j]
// ---------------------------------------------------------------------------
__global__ void scatter_kernel(const float* __restrict__ ow,
                               const int* __restrict__ cols,
                               int OC, int IC, int NOUT) {
    size_t n = (size_t)OC * NOUT;
    for (size_t t = (size_t)blockIdx.x * blockDim.x + threadIdx.x; t < n;
         t += (size_t)gridDim.x * blockDim.x) {
        int o = (int)(t / NOUT);
        int j = (int)(t % NOUT);
        int c = cols[j];
        g_wq[(size_t)o * IC + c] = ow[(size_t)o * NOUT + j];
    }
}

// ---------------------------------------------------------------------------
// Kernel 4: GEMM  C[t][o] = sum_k x[t][k] * wq[o][k] + bias[o]
// Classic 128x128x16 fp32 tile, 8x8 per thread, 256 threads/block.
// Both operands are K-contiguous (A row-major [T,IC], B row-major [OC,IC]).
// ---------------------------------------------------------------------------
#define BM 128
#define BN 128
#define BK 16
#define TM 8
#define TN 8

__global__ __launch_bounds__(256, 2)
void gemm_kernel(const float* __restrict__ A,   // x [T, IC]
                 const float* __restrict__ bias,
                 float* __restrict__ C,         // [T, OC]
                 int T, int OC, int IC) {
    __shared__ float As[BK][BM];
    __shared__ float Bs[BK][BN];

    const float* B = g_wq;

    int tid = threadIdx.x;
    int block_row = blockIdx.y * BM;  // token dim
    int block_col = blockIdx.x * BN;  // output-channel dim

    int tx = tid % 16;  // col group (TN cols each)
    int ty = tid / 16;  // row group (TM rows each)

    // Tile-load mapping: 128 rows x 16 floats = 512 float4; 2 per thread.
    int lr = tid / 4;        // 0..63
    int lc = (tid % 4) * 4;  // 0,4,8,12

    const float* Aptr = A + (size_t)block_row * IC;
    const float* Bptr = B + (size_t)block_col * IC;

    float acc[TM][TN];
    #pragma unroll
    for (int m = 0; m < TM; m++)
        #pragma unroll
        for (int n = 0; n < TN; n++) acc[m][n] = 0.f;

    for (int k0 = 0; k0 < IC; k0 += BK) {
        #pragma unroll
        for (int i = 0; i < 2; i++) {
            int r = lr + i * 64;
            float4 va = *reinterpret_cast<const float4*>(Aptr + (size_t)r * IC + k0 + lc);
            As[lc + 0][r] = va.x;
            As[lc + 1][r] = va.y;
            As[lc + 2][r] = va.z;
            As[lc + 3][r] = va.w;
            float4 vb = *reinterpret_cast<const float4*>(Bptr + (size_t)r * IC + k0 + lc);
            Bs[lc + 0][r] = vb.x;
            Bs[lc + 1][r] = vb.y;
            Bs[lc + 2][r] = vb.z;
            Bs[lc + 3][r] = vb.w;
        }
        __syncthreads();

        #pragma unroll
        for (int k = 0; k < BK; k++) {
            float a_reg[TM], b_reg[TN];
            // vectorized smem reads (32B each)
            float4 a0 = *reinterpret_cast<const float4*>(&As[k][ty * TM]);
            float4 a1 = *reinterpret_cast<const float4*>(&As[k][ty * TM + 4]);
            a_reg[0] = a0.x; a_reg[1] = a0.y; a_reg[2] = a0.z; a_reg[3] = a0.w;
            a_reg[4] = a1.x; a_reg[5] = a1.y; a_reg[6] = a1.z; a_reg[7] = a1.w;
            float4 b0 = *reinterpret_cast<const float4*>(&Bs[k][tx * TN]);
            float4 b1 = *reinterpret_cast<const float4*>(&Bs[k][tx * TN + 4]);
            b_reg[0] = b0.x; b_reg[1] = b0.y; b_reg[2] = b0.z; b_reg[3] = b0.w;
            b_reg[4] = b1.x; b_reg[5] = b1.y; b_reg[6] = b1.z; b_reg[7] = b1.w;
            #pragma unroll
            for (int m = 0; m < TM; m++)
                #pragma unroll
                for (int n = 0; n < TN; n++)
                    acc[m][n] += a_reg[m] * b_reg[n];
        }
        __syncthreads();
    }

    // Epilogue: add bias, write out.
    #pragma unroll
    for (int m = 0; m < TM; m++) {
        int row = block_row + ty * TM + m;
        float* crow = C + (size_t)row * OC + block_col + tx * TN;
        #pragma unroll
        for (int n = 0; n < TN; n++) {
            crow[n] = acc[m][n] + bias[block_col + tx * TN + n];
        }
    }
}

// ---------------------------------------------------------------------------
// Launch
// ---------------------------------------------------------------------------
extern "C" void kernel_launch(void* const* d_in, const int* in_sizes, int n_in,
                              void* d_out, int out_size) {
    const float* x    = (const float*)d_in[0];
    const float* w    = (const float*)d_in[1];
    const float* bias = (const float*)d_in[2];
    const float* ow   = (const float*)d_in[3];
    const int*   cols = (const int*)d_in[4];

    int OC   = in_sizes[2];
    int IC   = in_sizes[1] / OC;
    int T    = in_sizes[0] / IC;
    int NOUT = in_sizes[3] / OC;

    float* out = (float*)d_out;

    // 1) per-row stats
    rowstats_kernel<<<OC, 256>>>(w, IC);

    // 2) quantize dense weight
    {
        size_t n4 = (size_t)OC * IC / 4;
        int threads = 256;
        int blocks = (int)((n4 + threads - 1) / threads);
        if (blocks > 8192) blocks = 8192;
        quantize_kernel<<<blocks, threads>>>(w, OC, IC);
    }

    // 3) scatter outlier columns
    {
        size_t n = (size_t)OC * NOUT;
        int threads = 256;
        int blocks = (int)((n + threads - 1) / threads);
        if (blocks > 4096) blocks = 4096;
        scatter_kernel<<<blocks, threads>>>(ow, cols, OC, IC, NOUT);
    }

    // 4) GEMM + bias
    {
        dim3 grid(OC / BN, T / BM);
        gemm_kernel<<<grid, 256>>>(x, bias, out, T, OC, IC);
    }
}

// round 4
// speedup vs baseline: 2.8846x; 2.8846x over previous
#include <cuda_runtime.h>
#include <cuda_bf16.h>
#include <stdint.h>

// ---------------------------------------------------------------------------
// Dims: T=4096, IC=OC=4096, NOUT=204.
// K layout: [ x_hi(IC) | x_lo(IC) | Xo_hi(NOUT) | Xo_lo(NOUT) | Xo_hi(NOUT) | pad ]
// B layout: [ sign(IC) | sign(IC) | D'hi(NOUT)  | D'hi(NOUT)  | D'lo(NOUT)  | pad ]
// C[t][o] = (sum_k A'[t][k]*B'[o][k]) * s_eff[o] + bias[o]
// ---------------------------------------------------------------------------
#define MAX_OC 4096
#define MAX_IC 4096
#define MAXK   (2 * MAX_IC + 3 * 256)   // 8960 max padded K

__device__ __nv_bfloat16 g_A[(size_t)MAX_OC * MAXK];
__device__ __nv_bfloat16 g_B[(size_t)MAX_OC * MAXK];
__device__ float g_mean[MAX_OC];
__device__ float g_scale[MAX_OC];
__device__ float g_seff[MAX_OC];

// ---------------------------------------------------------------------------
// PTX helpers (sm_80-level only: cp.async, ldmatrix, mma.sync)
// ---------------------------------------------------------------------------
__device__ __forceinline__ uint32_t smem_u32(const void* p) {
    uint32_t a;
    asm("{ .reg .u64 t; cvta.to.shared.u64 t, %1; cvt.u32.u64 %0, t; }"
        : "=r"(a) : "l"(p));
    return a;
}
#define CP_ASYNC16(dst, src) \
    asm volatile("cp.async.cg.shared.global [%0], [%1], 16;" :: "r"(dst), "l"(src))
#define CP_COMMIT() asm volatile("cp.async.commit_group;" ::: "memory")
#define CP_WAIT(n)  asm volatile("cp.async.wait_group %0;" :: "n"(n) : "memory")

__device__ __forceinline__ void ldsm4(uint32_t* r, uint32_t addr) {
    asm volatile("ldmatrix.sync.aligned.m8n8.x4.shared.b16 {%0,%1,%2,%3}, [%4];"
                 : "=r"(r[0]), "=r"(r[1]), "=r"(r[2]), "=r"(r[3]) : "r"(addr));
}
__device__ __forceinline__ void mma16816(float* d, const uint32_t* a,
                                         uint32_t b0, uint32_t b1) {
    asm volatile(
        "mma.sync.aligned.m16n8k16.row.col.f32.bf16.bf16.f32 "
        "{%0,%1,%2,%3}, {%4,%5,%6,%7}, {%8,%9}, {%0,%1,%2,%3};"
        : "+f"(d[0]), "+f"(d[1]), "+f"(d[2]), "+f"(d[3])
        : "r"(a[0]), "r"(a[1]), "r"(a[2]), "r"(a[3]), "r"(b0), "r"(b1));
}
__device__ __forceinline__ uint32_t swz(uint32_t off) {
    return off ^ ((off >> 3) & 0x70);
}

// ---------------------------------------------------------------------------
// Kernel 1: per-output-row mean / mean-abs-dev; s_eff = max(scale, tiny).
// ---------------------------------------------------------------------------
__global__ void rowstats_kernel(const float* __restrict__ w, int IC) {
    int o = blockIdx.x;
    const float* row = w + (size_t)o * IC;
    __shared__ float red[256];
    int tid = threadIdx.x;

    float s = 0.f;
    for (int i = tid; i < IC; i += 256) s += row[i];
    red[tid] = s;
    __syncthreads();
    #pragma unroll
    for (int off = 128; off > 0; off >>= 1) {
        if (tid < off) red[tid] += red[tid + off];
        __syncthreads();
    }
    float mean = red[0] / (float)IC;
    __syncthreads();

    float s2 = 0.f;
    for (int i = tid; i < IC; i += 256) s2 += fabsf(row[i] - mean);
    red[tid] = s2;
    __syncthreads();
    #pragma unroll
    for (int off = 128; off > 0; off >>= 1) {
        if (tid < off) red[tid] += red[tid + off];
        __syncthreads();
    }
    if (tid == 0) {
        float sc = red[0] / (float)IC;
        g_mean[o]  = mean;
        g_scale[o] = sc;
        g_seff[o]  = fmaxf(sc, 1e-20f);
    }
}

// ---------------------------------------------------------------------------
// Kernel 2: B main segments = sign matrix (exact in bf16), duplicated.
// ---------------------------------------------------------------------------
__global__ void prepB_kernel(const float* __restrict__ w, int OC, int IC, int ktot) {
    size_t n4 = (size_t)OC * IC / 4;
    int ic4 = IC / 4;
    for (size_t idx = (size_t)blockIdx.x * blockDim.x + threadIdx.x; idx < n4;
         idx += (size_t)gridDim.x * blockDim.x) {
        int o = (int)(idx / ic4);
        int k = (int)(idx % ic4) * 4;
        float mean = g_mean[o];
        float4 v = reinterpret_cast<const float4*>(w)[idx];
        __nv_bfloat16 sg[4];
        float a;
        a = v.x - mean; sg[0] = __float2bfloat16_rn((a > 0.f) ? 1.f : ((a < 0.f) ? -1.f : 0.f));
        a = v.y - mean; sg[1] = __float2bfloat16_rn((a > 0.f) ? 1.f : ((a < 0.f) ? -1.f : 0.f));
        a = v.z - mean; sg[2] = __float2bfloat16_rn((a > 0.f) ? 1.f : ((a < 0.f) ? -1.f : 0.f));
        a = v.w - mean; sg[3] = __float2bfloat16_rn((a > 0.f) ? 1.f : ((a < 0.f) ? -1.f : 0.f));
        __nv_bfloat16* rowp = g_B + (size_t)o * ktot;
        *reinterpret_cast<uint2*>(rowp + k)      = *reinterpret_cast<uint2*>(sg);
        *reinterpret_cast<uint2*>(rowp + IC + k) = *reinterpret_cast<uint2*>(sg);
    }
}

// ---------------------------------------------------------------------------
// Kernel 3: B outlier segments: D' = (ow - sign*scale)/s_eff, hi/hi/lo + pad.
// ---------------------------------------------------------------------------
__global__ void scatterB_kernel(const float* __restrict__ w,
                                const float* __restrict__ ow,
                                const int* __restrict__ cols,
                                int OC, int IC, int NOUT, int ktot) {
    int ntask = (ktot - 2 * IC) - 2 * NOUT;  // NOUT + pad
    size_t n = (size_t)OC * ntask;
    for (size_t t = (size_t)blockIdx.x * blockDim.x + threadIdx.x; t < n;
         t += (size_t)gridDim.x * blockDim.x) {
        int o = (int)(t / ntask);
        int j = (int)(t % ntask);
        __nv_bfloat16* rowp = g_B + (size_t)o * ktot + 2 * IC;
        if (j < NOUT) {
            int c = cols[j];
            float a = w[(size_t)o * IC + c] - g_mean[o];
            float sgn = (a > 0.f) ? 1.f : ((a < 0.f) ? -1.f : 0.f);
            float dp = (ow[(size_t)o * NOUT + j] - sgn * g_scale[o]) / g_seff[o];
            __nv_bfloat16 hi = __float2bfloat16_rn(dp);
            __nv_bfloat16 lo = __float2bfloat16_rn(dp - __bfloat162float(hi));
            rowp[j]            = hi;
            rowp[NOUT + j]     = hi;
            rowp[2 * NOUT + j] = lo;
        } else {
            rowp[2 * NOUT + j] = __float2bfloat16_rn(0.f);  // pad tail
        }
    }
}

// ---------------------------------------------------------------------------
// Kernel 4: A main segments: x hi/lo split.
// ---------------------------------------------------------------------------
__global__ void prepA_kernel(const float* __restrict__ x, int T, int IC, int ktot) {
    size_t n4 = (size_t)T * IC / 4;
    int ic4 = IC / 4;
    for (size_t idx = (size_t)blockIdx.x * blockDim.x + threadIdx.x; idx < n4;
         idx += (size_t)gridDim.x * blockDim.x) {
        int t = (int)(idx / ic4);
        int k = (int)(idx % ic4) * 4;
        float4 v = reinterpret_cast<const float4*>(x)[idx];
        float q[4] = {v.x, v.y, v.z, v.w};
        __nv_bfloat16 hi[4], lo[4];
        #pragma unroll
        for (int i = 0; i < 4; i++) {
            hi[i] = __float2bfloat16_rn(q[i]);
            lo[i] = __float2bfloat16_rn(q[i] - __bfloat162float(hi[i]));
        }
        __nv_bfloat16* rowp = g_A + (size_t)t * ktot;
        *reinterpret_cast<uint2*>(rowp + k)      = *reinterpret_cast<uint2*>(hi);
        *reinterpret_cast<uint2*>(rowp + IC + k) = *reinterpret_cast<uint2*>(lo);
    }
}

// ---------------------------------------------------------------------------
// Kernel 5: A outlier segments: gathered x columns hi/lo/hi + pad.
// ---------------------------------------------------------------------------
__global__ void gatherA_kernel(const float* __restrict__ x,
                               const int* __restrict__ cols,
                               int T, int IC, int NOUT, int ktot) {
    int ntask = (ktot - 2 * IC) - 2 * NOUT;
    size_t n = (size_t)T * ntask;
    for (size_t t0 = (size_t)blockIdx.x * blockDim.x + threadIdx.x; t0 < n;
         t0 += (size_t)gridDim.x * blockDim.x) {
        int t = (int)(t0 / ntask);
        int j = (int)(t0 % ntask);
        __nv_bfloat16* rowp = g_A + (size_t)t * ktot + 2 * IC;
        if (j < NOUT) {
            int c = cols[j];
            float v = x[(size_t)t * IC + c];
            __nv_bfloat16 hi = __float2bfloat16_rn(v);
            __nv_bfloat16 lo = __float2bfloat16_rn(v - __bfloat162float(hi));
            rowp[j]            = hi;
            rowp[NOUT + j]     = lo;
            rowp[2 * NOUT + j] = hi;
        } else {
            rowp[2 * NOUT + j] = __float2bfloat16_rn(0.f);
        }
    }
}

// ---------------------------------------------------------------------------
// Kernel 6: GEMM via mma.sync bf16. BM=128, BN=256, BK=64, 8 warps (64x64),
// 3-stage cp.async pipeline, SW128-swizzled smem, epilogue scale+bias.
// ---------------------------------------------------------------------------
#define BM 128
#define BN 256
#define BK 64
#define NSTAGE 3
#define TILE_A_BYTES (BM * BK * 2)                  // 16 KB
#define TILE_B_BYTES (BN * BK * 2)                  // 32 KB
#define STAGE_BYTES  (TILE_A_BYTES + TILE_B_BYTES)  // 48 KB
#define GEMM_SMEM    (NSTAGE * STAGE_BYTES + 1024)  // 145 KB + align

__device__ __forceinline__ void load_stage(uint32_t abase, uint32_t bbase,
                                           const char* Ag, const char* Bg,
                                           int kt, int tid, size_t rowbytes) {
    const char* asrc = Ag + (size_t)kt * (BK * 2);
    #pragma unroll
    for (int i = 0; i < 4; i++) {
        int idx = tid + i * 256;
        int r = idx >> 3, c = idx & 7;
        CP_ASYNC16(abase + swz((uint32_t)(r * 128 + c * 16)),
                   asrc + (size_t)r * rowbytes + c * 16);
    }
    const char* bsrc = Bg + (size_t)kt * (BK * 2);
    #pragma unroll
    for (int i = 0; i < 8; i++) {
        int idx = tid + i * 256;
        int r = idx >> 3, c = idx & 7;
        CP_ASYNC16(bbase + swz((uint32_t)(r * 128 + c * 16)),
                   bsrc + (size_t)r * rowbytes + c * 16);
    }
}

__global__ __launch_bounds__(256)
void gemm_mma(const float* __restrict__ bias, float* __restrict__ C,
              int T, int OC, int ktot) {
    extern __shared__ char sm_raw[];
    uint32_t raw = smem_u32(sm_raw);
    uint32_t sbase = (raw + 1023u) & ~1023u;

    const int tid = threadIdx.x;
    const int lane = tid & 31, wid = tid >> 5;
    const int wm = (wid & 1) * 64;
    const int wn = (wid >> 1) * 64;

    const char* Ag = reinterpret_cast<const char*>(g_A + (size_t)(blockIdx.y * BM) * ktot);
    const char* Bg = reinterpret_cast<const char*>(g_B + (size_t)(blockIdx.x * BN) * ktot);
    const size_t rowbytes = (size_t)ktot * 2;

    float acc[4][8][4];
    #pragma unroll
    for (int mi = 0; mi < 4; mi++)
        #pragma unroll
        for (int ni = 0; ni < 8; ni++)
            #pragma unroll
            for (int e = 0; e < 4; e++) acc[mi][ni][e] = 0.f;

    const int nkt = ktot / BK;

    #pragma unroll
    for (int s = 0; s < NSTAGE - 1; s++) {
        load_stage(sbase + s * STAGE_BYTES, sbase + s * STAGE_BYTES + TILE_A_BYTES,
                   Ag, Bg, s, tid, rowbytes);
        CP_COMMIT();
    }

    // ldmatrix lane addressing pieces (constant over k-tiles)
    const int lrow = lane & 15;            // row within 16
    const int lkoff = (lane >> 4) * 16;    // byte offset for k-half

    for (int kt = 0; kt < nkt; kt++) {
        CP_WAIT(NSTAGE - 2);
        __syncthreads();

        int pf = kt + NSTAGE - 1;
        if (pf < nkt) {
            int s = pf % NSTAGE;
            load_stage(sbase + s * STAGE_BYTES,
                       sbase + s * STAGE_BYTES + TILE_A_BYTES,
                       Ag, Bg, pf, tid, rowbytes);
        }
        CP_COMMIT();

        uint32_t abase = sbase + (kt % NSTAGE) * STAGE_BYTES;
        uint32_t bbase = abase + TILE_A_BYTES;

        #pragma unroll
        for (int ks = 0; ks < 4; ks++) {
            uint32_t afrag[4][4], bfrag[4][4];
            #pragma unroll
            for (int mi = 0; mi < 4; mi++) {
                uint32_t off = (uint32_t)((wm + mi * 16 + lrow) * 128 + ks * 32 + lkoff);
                ldsm4(afrag[mi], abase + swz(off));
            }
            #pragma unroll
            for (int ni = 0; ni < 4; ni++) {
                uint32_t off = (uint32_t)((wn + ni * 16 + lrow) * 128 + ks * 32 + lkoff);
                ldsm4(bfrag[ni], bbase + swz(off));
            }
            #pragma unroll
            for (int mi = 0; mi < 4; mi++) {
                #pragma unroll
                for (int ni = 0; ni < 4; ni++) {
                    mma16816(acc[mi][2 * ni],     afrag[mi], bfrag[ni][0], bfrag[ni][2]);
                    mma16816(acc[mi][2 * ni + 1], afrag[mi], bfrag[ni][1], bfrag[ni][3]);
                }
            }
        }
    }

    // Epilogue: C = acc * s_eff[col] + bias[col]
    int colb = blockIdx.x * BN + wn + (lane & 3) * 2;
    int rowb = blockIdx.y * BM + wm + (lane >> 2);
    #pragma unroll
    for (int ni = 0; ni < 8; ni++) {
        int col = colb + ni * 8;
        float s0 = g_seff[col],     s1 = g_seff[col + 1];
        float b0 = bias[col],       b1 = bias[col + 1];
        #pragma unroll
        for (int mi = 0; mi < 4; mi++) {
            int row = rowb + mi * 16;
            float2 v0 = make_float2(acc[mi][ni][0] * s0 + b0,
                                    acc[mi][ni][1] * s1 + b1);
            float2 v1 = make_float2(acc[mi][ni][2] * s0 + b0,
                                    acc[mi][ni][3] * s1 + b1);
            *reinterpret_cast<float2*>(C + (size_t)row * OC + col)       = v0;
            *reinterpret_cast<float2*>(C + (size_t)(row + 8) * OC + col) = v1;
        }
    }
}

// ---------------------------------------------------------------------------
// Launch
// ---------------------------------------------------------------------------
extern "C" void kernel_launch(void* const* d_in, const int* in_sizes, int n_in,
                              void* d_out, int out_size) {
    const float* x    = (const float*)d_in[0];
    const float* w    = (const float*)d_in[1];
    const float* bias = (const float*)d_in[2];
    const float* ow   = (const float*)d_in[3];
    const int*   cols = (const int*)d_in[4];

    int OC   = in_sizes[2];
    int IC   = in_sizes[1] / OC;
    int T    = in_sizes[0] / IC;
    int NOUT = in_sizes[3] / OC;
    int ktot = (2 * IC + 3 * NOUT + 63) & ~63;

    float* out = (float*)d_out;

    rowstats_kernel<<<OC, 256>>>(w, IC);

    {
        size_t n4 = (size_t)OC * IC / 4;
        int blocks = (int)((n4 + 255) / 256);
        if (blocks > 8192) blocks = 8192;
        prepB_kernel<<<blocks, 256>>>(w, OC, IC, ktot);
    }
    {
        int ntask = (ktot - 2 * IC) - 2 * NOUT;
        size_t n = (size_t)OC * ntask;
        int blocks = (int)((n + 255) / 256);
        if (blocks > 4096) blocks = 4096;
        scatterB_kernel<<<blocks, 256>>>(w, ow, cols, OC, IC, NOUT, ktot);
    }
    {
        size_t n4 = (size_t)T * IC / 4;
        int blocks = (int)((n4 + 255) / 256);
        if (blocks > 8192) blocks = 8192;
        prepA_kernel<<<blocks, 256>>>(x, T, IC, ktot);
    }
    {
        int ntask = (ktot - 2 * IC) - 2 * NOUT;
        size_t n = (size_t)T * ntask;
        int blocks = (int)((n + 255) / 256);
        if (blocks > 4096) blocks = 4096;
        gatherA_kernel<<<blocks, 256>>>(x, cols, T, IC, NOUT, ktot);
    }
    {
        static bool attr_set = false;
        if (!attr_set) {
            cudaFuncSetAttribute(gemm_mma,
                                 cudaFuncAttributeMaxDynamicSharedMemorySize,
                                 GEMM_SMEM);
            attr_set = true;
        }
        dim3 grid(OC / BN, T / BM);
        gemm_mma<<<grid, 256, GEMM_SMEM>>>(bias, out, T, OC, ktot);
    }
}

// round 9
// speedup vs baseline: 3.2831x; 1.1381x over previous
#include <cuda_runtime.h>
#include <cuda_bf16.h>
#include <stdint.h>

// ---------------------------------------------------------------------------
// Dims: T=4096, IC=OC=4096, NOUT=204.
// K layout: [ x_hi(IC) | x_lo(IC) | Xo_hi(NOUT) | Xo_lo(NOUT) | Xo_hi(NOUT) | pad ]
// B layout: [ sign(IC) | sign(IC) | D'hi(NOUT)  | D'hi(NOUT)  | D'lo(NOUT)  | pad ]
// C[t][o] = (sum_k A'[t][k]*B'[o][k]) * s_eff[o] + bias[o]
// ---------------------------------------------------------------------------
#define MAX_OC 4096
#define MAX_IC 4096
#define MAXK   (2 * MAX_IC + 3 * 256)   // 8960 max padded K

__device__ __nv_bfloat16 g_A[(size_t)MAX_OC * MAXK];
__device__ __nv_bfloat16 g_B[(size_t)MAX_OC * MAXK];
__device__ float g_mean[MAX_OC];
__device__ float g_scale[MAX_OC];
__device__ float g_seff[MAX_OC];

// ---------------------------------------------------------------------------
// PTX helpers (sm_80-level only: cp.async, ldmatrix, mma.sync)
// ---------------------------------------------------------------------------
__device__ __forceinline__ uint32_t smem_u32(const void* p) {
    uint32_t a;
    asm("{ .reg .u64 t; cvta.to.shared.u64 t, %1; cvt.u32.u64 %0, t; }"
        : "=r"(a) : "l"(p));
    return a;
}
#define CP_ASYNC16(dst, src) \
    asm volatile("cp.async.cg.shared.global [%0], [%1], 16;" :: "r"(dst), "l"(src))
#define CP_COMMIT() asm volatile("cp.async.commit_group;" ::: "memory")
#define CP_WAIT(n)  asm volatile("cp.async.wait_group %0;" :: "n"(n) : "memory")

__device__ __forceinline__ void ldsm4(uint32_t* r, uint32_t addr) {
    asm volatile("ldmatrix.sync.aligned.m8n8.x4.shared.b16 {%0,%1,%2,%3}, [%4];"
                 : "=r"(r[0]), "=r"(r[1]), "=r"(r[2]), "=r"(r[3]) : "r"(addr));
}
__device__ __forceinline__ void mma16816(float* d, const uint32_t* a,
                                         uint32_t b0, uint32_t b1) {
    asm volatile(
        "mma.sync.aligned.m16n8k16.row.col.f32.bf16.bf16.f32 "
        "{%0,%1,%2,%3}, {%4,%5,%6,%7}, {%8,%9}, {%0,%1,%2,%3};"
        : "+f"(d[0]), "+f"(d[1]), "+f"(d[2]), "+f"(d[3])
        : "r"(a[0]), "r"(a[1]), "r"(a[2]), "r"(a[3]), "r"(b0), "r"(b1));
}
__device__ __forceinline__ uint32_t swz(uint32_t off) {
    return off ^ ((off >> 3) & 0x70);
}

// ---------------------------------------------------------------------------
// Kernel 1: per-output-row mean / mean-abs-dev; s_eff = max(scale, tiny).
// ---------------------------------------------------------------------------
__global__ void rowstats_kernel(const float* __restrict__ w, int IC) {
    int o = blockIdx.x;
    const float* row = w + (size_t)o * IC;
    __shared__ float red[256];
    int tid = threadIdx.x;

    float s = 0.f;
    for (int i = tid; i < IC; i += 256) s += row[i];
    red[tid] = s;
    __syncthreads();
    #pragma unroll
    for (int off = 128; off > 0; off >>= 1) {
        if (tid < off) red[tid] += red[tid + off];
        __syncthreads();
    }
    float mean = red[0] / (float)IC;
    __syncthreads();

    float s2 = 0.f;
    for (int i = tid; i < IC; i += 256) s2 += fabsf(row[i] - mean);
    red[tid] = s2;
    __syncthreads();
    #pragma unroll
    for (int off = 128; off > 0; off >>= 1) {
        if (tid < off) red[tid] += red[tid + off];
        __syncthreads();
    }
    if (tid == 0) {
        float sc = red[0] / (float)IC;
        g_mean[o]  = mean;
        g_scale[o] = sc;
        g_seff[o]  = fmaxf(sc, 1e-20f);
    }
}

// ---------------------------------------------------------------------------
// Kernel 2: B main segments = sign matrix (exact in bf16), duplicated.
// ---------------------------------------------------------------------------
__global__ void prepB_kernel(const float* __restrict__ w, int OC, int IC, int ktot) {
    size_t n4 = (size_t)OC * IC / 4;
    int ic4 = IC / 4;
    for (size_t idx = (size_t)blockIdx.x * blockDim.x + threadIdx.x; idx < n4;
         idx += (size_t)gridDim.x * blockDim.x) {
        int o = (int)(idx / ic4);
        int k = (int)(idx % ic4) * 4;
        float mean = g_mean[o];
        float4 v = reinterpret_cast<const float4*>(w)[idx];
        __nv_bfloat16 sg[4];
        float a;
        a = v.x - mean; sg[0] = __float2bfloat16_rn((a > 0.f) ? 1.f : ((a < 0.f) ? -1.f : 0.f));
        a = v.y - mean; sg[1] = __float2bfloat16_rn((a > 0.f) ? 1.f : ((a < 0.f) ? -1.f : 0.f));
        a = v.z - mean; sg[2] = __float2bfloat16_rn((a > 0.f) ? 1.f : ((a < 0.f) ? -1.f : 0.f));
        a = v.w - mean; sg[3] = __float2bfloat16_rn((a > 0.f) ? 1.f : ((a < 0.f) ? -1.f : 0.f));
        __nv_bfloat16* rowp = g_B + (size_t)o * ktot;
        *reinterpret_cast<uint2*>(rowp + k)      = *reinterpret_cast<uint2*>(sg);
        *reinterpret_cast<uint2*>(rowp + IC + k) = *reinterpret_cast<uint2*>(sg);
    }
}

// ---------------------------------------------------------------------------
// Kernel 3: B outlier segments: D' = (ow - sign*scale)/s_eff, hi/hi/lo + pad.
// ---------------------------------------------------------------------------
__global__ void scatterB_kernel(const float* __restrict__ w,
                                const float* __restrict__ ow,
                                const int* __restrict__ cols,
                                int OC, int IC, int NOUT, int ktot) {
    int ntask = (ktot - 2 * IC) - 2 * NOUT;  // NOUT + pad
    size_t n = (size_t)OC * ntask;
    for (size_t t = (size_t)blockIdx.x * blockDim.x + threadIdx.x; t < n;
         t += (size_t)gridDim.x * blockDim.x) {
        int o = (int)(t / ntask);
        int j = (int)(t % ntask);
        __nv_bfloat16* rowp = g_B + (size_t)o * ktot + 2 * IC;
        if (j < NOUT) {
            int c = cols[j];
            float a = w[(size_t)o * IC + c] - g_mean[o];
            float sgn = (a > 0.f) ? 1.f : ((a < 0.f) ? -1.f : 0.f);
            float dp = (ow[(size_t)o * NOUT + j] - sgn * g_scale[o]) / g_seff[o];
            __nv_bfloat16 hi = __float2bfloat16_rn(dp);
            __nv_bfloat16 lo = __float2bfloat16_rn(dp - __bfloat162float(hi));
            rowp[j]            = hi;
            rowp[NOUT + j]     = hi;
            rowp[2 * NOUT + j] = lo;
        } else {
            rowp[2 * NOUT + j] = __float2bfloat16_rn(0.f);  // pad tail
        }
    }
}

// ---------------------------------------------------------------------------
// Kernel 4: A main segments: x hi/lo split.
// ---------------------------------------------------------------------------
__global__ void prepA_kernel(const float* __restrict__ x, int T, int IC, int ktot) {
    size_t n4 = (size_t)T * IC / 4;
    int ic4 = IC / 4;
    for (size_t idx = (size_t)blockIdx.x * blockDim.x + threadIdx.x; idx < n4;
         idx += (size_t)gridDim.x * blockDim.x) {
        int t = (int)(idx / ic4);
        int k = (int)(idx % ic4) * 4;
        float4 v = reinterpret_cast<const float4*>(x)[idx];
        float q[4] = {v.x, v.y, v.z, v.w};
        __nv_bfloat16 hi[4], lo[4];
        #pragma unroll
        for (int i = 0; i < 4; i++) {
            hi[i] = __float2bfloat16_rn(q[i]);
            lo[i] = __float2bfloat16_rn(q[i] - __bfloat162float(hi[i]));
        }
        __nv_bfloat16* rowp = g_A + (size_t)t * ktot;
        *reinterpret_cast<uint2*>(rowp + k)      = *reinterpret_cast<uint2*>(hi);
        *reinterpret_cast<uint2*>(rowp + IC + k) = *reinterpret_cast<uint2*>(lo);
    }
}

// ---------------------------------------------------------------------------
// Kernel 5: A outlier segments: gathered x columns hi/lo/hi + pad.
// ---------------------------------------------------------------------------
__global__ void gatherA_kernel(const float* __restrict__ x,
                               const int* __restrict__ cols,
                               int T, int IC, int NOUT, int ktot) {
    int ntask = (ktot - 2 * IC) - 2 * NOUT;
    size_t n = (size_t)T * ntask;
    for (size_t t0 = (size_t)blockIdx.x * blockDim.x + threadIdx.x; t0 < n;
         t0 += (size_t)gridDim.x * blockDim.x) {
        int t = (int)(t0 / ntask);
        int j = (int)(t0 % ntask);
        __nv_bfloat16* rowp = g_A + (size_t)t * ktot + 2 * IC;
        if (j < NOUT) {
            int c = cols[j];
            float v = x[(size_t)t * IC + c];
            __nv_bfloat16 hi = __float2bfloat16_rn(v);
            __nv_bfloat16 lo = __float2bfloat16_rn(v - __bfloat162float(hi));
            rowp[j]            = hi;
            rowp[NOUT + j]     = lo;
            rowp[2 * NOUT + j] = hi;
        } else {
            rowp[2 * NOUT + j] = __float2bfloat16_rn(0.f);
        }
    }
}

// ---------------------------------------------------------------------------
// Kernel 6: GEMM via mma.sync bf16. BM=128, BN=256, BK=64, 8 warps (64x64),
// 4-stage cp.async pipeline, SW128-swizzled smem, register double-buffered
// ldmatrix fragments (ks-level), epilogue scale+bias.
// ---------------------------------------------------------------------------
#define BM 128
#define BN 256
#define BK 64
#define NSTAGE 4
#define TILE_A_BYTES (BM * BK * 2)                  // 16 KB
#define TILE_B_BYTES (BN * BK * 2)                  // 32 KB
#define STAGE_BYTES  (TILE_A_BYTES + TILE_B_BYTES)  // 48 KB
#define GEMM_SMEM    (NSTAGE * STAGE_BYTES + 1024)  // 193 KB

__device__ __forceinline__ void load_stage(uint32_t abase, uint32_t bbase,
                                           const char* Ag, const char* Bg,
                                           int kt, int tid, size_t rowbytes) {
    const char* asrc = Ag + (size_t)kt * (BK * 2);
    #pragma unroll
    for (int i = 0; i < 4; i++) {
        int idx = tid + i * 256;
        int r = idx >> 3, c = idx & 7;
        CP_ASYNC16(abase + swz((uint32_t)(r * 128 + c * 16)),
                   asrc + (size_t)r * rowbytes + c * 16);
    }
    const char* bsrc = Bg + (size_t)kt * (BK * 2);
    #pragma unroll
    for (int i = 0; i < 8; i++) {
        int idx = tid + i * 256;
        int r = idx >> 3, c = idx & 7;
        CP_ASYNC16(bbase + swz((uint32_t)(r * 128 + c * 16)),
                   bsrc + (size_t)r * rowbytes + c * 16);
    }
}

__global__ __launch_bounds__(256, 1)
void gemm_mma(const float* __restrict__ bias, float* __restrict__ C,
              int T, int OC, int ktot) {
    extern __shared__ char sm_raw[];
    uint32_t raw = smem_u32(sm_raw);
    uint32_t sbase = (raw + 1023u) & ~1023u;

    const int tid = threadIdx.x;
    const int lane = tid & 31, wid = tid >> 5;
    const int wm = (wid & 1) * 64;
    const int wn = (wid >> 1) * 64;

    const char* Ag = reinterpret_cast<const char*>(g_A + (size_t)(blockIdx.y * BM) * ktot);
    const char* Bg = reinterpret_cast<const char*>(g_B + (size_t)(blockIdx.x * BN) * ktot);
    const size_t rowbytes = (size_t)ktot * 2;

    float acc[4][8][4];
    #pragma unroll
    for (int mi = 0; mi < 4; mi++)
        #pragma unroll
        for (int ni = 0; ni < 8; ni++)
            #pragma unroll
            for (int e = 0; e < 4; e++) acc[mi][ni][e] = 0.f;

    const int nkt = ktot / BK;

    #pragma unroll
    for (int s = 0; s < NSTAGE - 1; s++) {
        load_stage(sbase + s * STAGE_BYTES, sbase + s * STAGE_BYTES + TILE_A_BYTES,
                   Ag, Bg, s, tid, rowbytes);
        CP_COMMIT();
    }

    // ldmatrix lane addressing pieces (constant over k-tiles)
    const int lrow = lane & 15;            // row within 16
    const int lkoff = (lane >> 4) * 16;    // byte offset for k-half
    const uint32_t arowoff = (uint32_t)((wm + lrow) * 128 + lkoff);
    const uint32_t browoff = (uint32_t)((wn + lrow) * 128 + lkoff);

    uint32_t afrag[2][4][4], bfrag[2][4][4];

    for (int kt = 0; kt < nkt; kt++) {
        CP_WAIT(NSTAGE - 2);
        __syncthreads();

        int pf = kt + NSTAGE - 1;
        if (pf < nkt) {
            int s = pf % NSTAGE;
            load_stage(sbase + s * STAGE_BYTES,
                       sbase + s * STAGE_BYTES + TILE_A_BYTES,
                       Ag, Bg, pf, tid, rowbytes);
        }
        CP_COMMIT();

        uint32_t abase = sbase + (kt % NSTAGE) * STAGE_BYTES;
        uint32_t bbase = abase + TILE_A_BYTES;

        // Preload ks=0 fragments into buffer 0.
        #pragma unroll
        for (int mi = 0; mi < 4; mi++)
            ldsm4(afrag[0][mi], abase + swz(arowoff + (uint32_t)(mi * 16 * 128)));
        #pragma unroll
        for (int ni = 0; ni < 4; ni++)
            ldsm4(bfrag[0][ni], bbase + swz(browoff + (uint32_t)(ni * 16 * 128)));

        #pragma unroll
        for (int ks = 0; ks < 4; ks++) {
            int cur = ks & 1;
            int nxt = cur ^ 1;
            if (ks < 3) {
                uint32_t ko = (uint32_t)((ks + 1) * 32);
                #pragma unroll
                for (int mi = 0; mi < 4; mi++)
                    ldsm4(afrag[nxt][mi],
                          abase + swz(arowoff + ko + (uint32_t)(mi * 16 * 128)));
                #pragma unroll
                for (int ni = 0; ni < 4; ni++)
                    ldsm4(bfrag[nxt][ni],
                          bbase + swz(browoff + ko + (uint32_t)(ni * 16 * 128)));
            }
            #pragma unroll
            for (int mi = 0; mi < 4; mi++) {
                #pragma unroll
                for (int ni = 0; ni < 4; ni++) {
                    mma16816(acc[mi][2 * ni],     afrag[cur][mi],
                             bfrag[cur][ni][0], bfrag[cur][ni][2]);
                    mma16816(acc[mi][2 * ni + 1], afrag[cur][mi],
                             bfrag[cur][ni][1], bfrag[cur][ni][3]);
                }
            }
        }
    }

    // Epilogue: C = acc * s_eff[col] + bias[col]
    int colb = blockIdx.x * BN + wn + (lane & 3) * 2;
    int rowb = blockIdx.y * BM + wm + (lane >> 2);
    #pragma unroll
    for (int ni = 0; ni < 8; ni++) {
        int col = colb + ni * 8;
        float s0 = g_seff[col],     s1 = g_seff[col + 1];
        float b0 = bias[col],       b1 = bias[col + 1];
        #pragma unroll
        for (int mi = 0; mi < 4; mi++) {
            int row = rowb + mi * 16;
            float2 v0 = make_float2(acc[mi][ni][0] * s0 + b0,
                                    acc[mi][ni][1] * s1 + b1);
            float2 v1 = make_float2(acc[mi][ni][2] * s0 + b0,
                                    acc[mi][ni][3] * s1 + b1);
            *reinterpret_cast<float2*>(C + (size_t)row * OC + col)       = v0;
            *reinterpret_cast<float2*>(C + (size_t)(row + 8) * OC + col) = v1;
        }
    }
}

// ---------------------------------------------------------------------------
// Launch
// ---------------------------------------------------------------------------
extern "C" void kernel_launch(void* const* d_in, const int* in_sizes, int n_in,
                              void* d_out, int out_size) {
    const float* x    = (const float*)d_in[0];
    const float* w    = (const float*)d_in[1];
    const float* bias = (const float*)d_in[2];
    const float* ow   = (const float*)d_in[3];
    const int*   cols = (const int*)d_in[4];

    int OC   = in_sizes[2];
    int IC   = in_sizes[1] / OC;
    int T    = in_sizes[0] / IC;
    int NOUT = in_sizes[3] / OC;
    int ktot = (2 * IC + 3 * NOUT + 63) & ~63;

    float* out = (float*)d_out;

    rowstats_kernel<<<OC, 256>>>(w, IC);

    {
        size_t n4 = (size_t)OC * IC / 4;
        int blocks = (int)((n4 + 255) / 256);
        if (blocks > 8192) blocks = 8192;
        prepB_kernel<<<blocks, 256>>>(w, OC, IC, ktot);
    }
    {
        int ntask = (ktot - 2 * IC) - 2 * NOUT;
        size_t n = (size_t)OC * ntask;
        int blocks = (int)((n + 255) / 256);
        if (blocks > 4096) blocks = 4096;
        scatterB_kernel<<<blocks, 256>>>(w, ow, cols, OC, IC, NOUT, ktot);
    }
    {
        size_t n4 = (size_t)T * IC / 4;
        int blocks = (int)((n4 + 255) / 256);
        if (blocks > 8192) blocks = 8192;
        prepA_kernel<<<blocks, 256>>>(x, T, IC, ktot);
    }
    {
        int ntask = (ktot - 2 * IC) - 2 * NOUT;
        size_t n = (size_t)T * ntask;
        int blocks = (int)((n + 255) / 256);
        if (blocks > 4096) blocks = 4096;
        gatherA_kernel<<<blocks, 256>>>(x, cols, T, IC, NOUT, ktot);
    }
    {
        static bool attr_set = false;
        if (!attr_set) {
            cudaFuncSetAttribute(gemm_mma,
                                 cudaFuncAttributeMaxDynamicSharedMemorySize,
                                 GEMM_SMEM);
            attr_set = true;
        }
        dim3 grid(OC / BN, T / BM);
        gemm_mma<<<grid, 256, GEMM_SMEM>>>(bias, out, T, OC, ktot);
    }
}

// round 10
// speedup vs baseline: 3.8639x; 1.1769x over previous
#include <cuda_runtime.h>
#include <cuda_bf16.h>
#include <stdint.h>

// ---------------------------------------------------------------------------
// Dims: T=4096, IC=OC=4096, NOUT=204.
// A layout [T,  ktotA]: [ x_hi(IC) | x_lo(IC) | Xo_hi | Xo_lo | Xo_hi | pad ]
// B layout [OC, ktotB]: [ sign(IC) | D'hi | D'hi | D'lo | pad ]
//   (sign stored ONCE; GEMM multiplies one B tile against both A_hi and A_lo)
// C[t][o] = (sum_k A'[t][k]*B'[o][k]) * s_eff[o] + bias[o]
// ---------------------------------------------------------------------------
#define MAX_OC 4096
#define MAX_IC 4096
#define MAXKA  (2 * MAX_IC + 3 * 256)   // 8960
#define MAXKB  (MAX_IC + 3 * 256)       // 4864

__device__ __nv_bfloat16 g_A[(size_t)MAX_OC * MAXKA];
__device__ __nv_bfloat16 g_B[(size_t)MAX_OC * MAXKB];
__device__ float g_mean[MAX_OC];
__device__ float g_scale[MAX_OC];
__device__ float g_seff[MAX_OC];

// ---------------------------------------------------------------------------
// PTX helpers (sm_80-level only: cp.async, ldmatrix, mma.sync)
// ---------------------------------------------------------------------------
__device__ __forceinline__ uint32_t smem_u32(const void* p) {
    uint32_t a;
    asm("{ .reg .u64 t; cvta.to.shared.u64 t, %1; cvt.u32.u64 %0, t; }"
        : "=r"(a) : "l"(p));
    return a;
}
#define CP_ASYNC16(dst, src) \
    asm volatile("cp.async.cg.shared.global [%0], [%1], 16;" :: "r"(dst), "l"(src))
#define CP_COMMIT() asm volatile("cp.async.commit_group;" ::: "memory")
#define CP_WAIT(n)  asm volatile("cp.async.wait_group %0;" :: "n"(n) : "memory")

__device__ __forceinline__ void ldsm4(uint32_t* r, uint32_t addr) {
    asm volatile("ldmatrix.sync.aligned.m8n8.x4.shared.b16 {%0,%1,%2,%3}, [%4];"
                 : "=r"(r[0]), "=r"(r[1]), "=r"(r[2]), "=r"(r[3]) : "r"(addr));
}
__device__ __forceinline__ void mma16816(float* d, const uint32_t* a,
                                         uint32_t b0, uint32_t b1) {
    asm volatile(
        "mma.sync.aligned.m16n8k16.row.col.f32.bf16.bf16.f32 "
        "{%0,%1,%2,%3}, {%4,%5,%6,%7}, {%8,%9}, {%0,%1,%2,%3};"
        : "+f"(d[0]), "+f"(d[1]), "+f"(d[2]), "+f"(d[3])
        : "r"(a[0]), "r"(a[1]), "r"(a[2]), "r"(a[3]), "r"(b0), "r"(b1));
}
__device__ __forceinline__ uint32_t swz(uint32_t off) {
    return off ^ ((off >> 3) & 0x70);
}

// ---------------------------------------------------------------------------
// Kernel 1: per-output-row mean / mean-abs-dev; s_eff = max(scale, tiny).
// ---------------------------------------------------------------------------
__global__ void rowstats_kernel(const float* __restrict__ w, int IC) {
    int o = blockIdx.x;
    const float* row = w + (size_t)o * IC;
    __shared__ float red[256];
    int tid = threadIdx.x;

    float s = 0.f;
    for (int i = tid; i < IC; i += 256) s += row[i];
    red[tid] = s;
    __syncthreads();
    #pragma unroll
    for (int off = 128; off > 0; off >>= 1) {
        if (tid < off) red[tid] += red[tid + off];
        __syncthreads();
    }
    float mean = red[0] / (float)IC;
    __syncthreads();

    float s2 = 0.f;
    for (int i = tid; i < IC; i += 256) s2 += fabsf(row[i] - mean);
    red[tid] = s2;
    __syncthreads();
    #pragma unroll
    for (int off = 128; off > 0; off >>= 1) {
        if (tid < off) red[tid] += red[tid + off];
        __syncthreads();
    }
    if (tid == 0) {
        float sc = red[0] / (float)IC;
        g_mean[o]  = mean;
        g_scale[o] = sc;
        g_seff[o]  = fmaxf(sc, 1e-20f);
    }
}

// ---------------------------------------------------------------------------
// Kernel 2: B main segment = sign matrix (exact in bf16), stored ONCE.
// ---------------------------------------------------------------------------
__global__ void prepB_kernel(const float* __restrict__ w, int OC, int IC, int ktotB) {
    size_t n4 = (size_t)OC * IC / 4;
    int ic4 = IC / 4;
    for (size_t idx = (size_t)blockIdx.x * blockDim.x + threadIdx.x; idx < n4;
         idx += (size_t)gridDim.x * blockDim.x) {
        int o = (int)(idx / ic4);
        int k = (int)(idx % ic4) * 4;
        float mean = g_mean[o];
        float4 v = reinterpret_cast<const float4*>(w)[idx];
        __nv_bfloat16 sg[4];
        float a;
        a = v.x - mean; sg[0] = __float2bfloat16_rn((a > 0.f) ? 1.f : ((a < 0.f) ? -1.f : 0.f));
        a = v.y - mean; sg[1] = __float2bfloat16_rn((a > 0.f) ? 1.f : ((a < 0.f) ? -1.f : 0.f));
        a = v.z - mean; sg[2] = __float2bfloat16_rn((a > 0.f) ? 1.f : ((a < 0.f) ? -1.f : 0.f));
        a = v.w - mean; sg[3] = __float2bfloat16_rn((a > 0.f) ? 1.f : ((a < 0.f) ? -1.f : 0.f));
        __nv_bfloat16* rowp = g_B + (size_t)o * ktotB;
        *reinterpret_cast<uint2*>(rowp + k) = *reinterpret_cast<uint2*>(sg);
    }
}

// ---------------------------------------------------------------------------
// Kernel 3: B outlier tail at offset IC: D' = (ow - sign*scale)/s_eff,
// hi/hi/lo + pad.
// ---------------------------------------------------------------------------
__global__ void scatterB_kernel(const float* __restrict__ w,
                                const float* __restrict__ ow,
                                const int* __restrict__ cols,
                                int OC, int IC, int NOUT, int ktotB) {
    int ntask = (ktotB - IC) - 2 * NOUT;  // NOUT + pad
    size_t n = (size_t)OC * ntask;
    for (size_t t = (size_t)blockIdx.x * blockDim.x + threadIdx.x; t < n;
         t += (size_t)gridDim.x * blockDim.x) {
        int o = (int)(t / ntask);
        int j = (int)(t % ntask);
        __nv_bfloat16* rowp = g_B + (size_t)o * ktotB + IC;
        if (j < NOUT) {
            int c = cols[j];
            float a = w[(size_t)o * IC + c] - g_mean[o];
            float sgn = (a > 0.f) ? 1.f : ((a < 0.f) ? -1.f : 0.f);
            float dp = (ow[(size_t)o * NOUT + j] - sgn * g_scale[o]) / g_seff[o];
            __nv_bfloat16 hi = __float2bfloat16_rn(dp);
            __nv_bfloat16 lo = __float2bfloat16_rn(dp - __bfloat162float(hi));
            rowp[j]            = hi;
            rowp[NOUT + j]     = hi;
            rowp[2 * NOUT + j] = lo;
        } else {
            rowp[2 * NOUT + j] = __float2bfloat16_rn(0.f);  // pad tail
        }
    }
}

// ---------------------------------------------------------------------------
// Kernel 4: A main segments: x hi/lo split.
// ---------------------------------------------------------------------------
__global__ void prepA_kernel(const float* __restrict__ x, int T, int IC, int ktotA) {
    size_t n4 = (size_t)T * IC / 4;
    int ic4 = IC / 4;
    for (size_t idx = (size_t)blockIdx.x * blockDim.x + threadIdx.x; idx < n4;
         idx += (size_t)gridDim.x * blockDim.x) {
        int t = (int)(idx / ic4);
        int k = (int)(idx % ic4) * 4;
        float4 v = reinterpret_cast<const float4*>(x)[idx];
        float q[4] = {v.x, v.y, v.z, v.w};
        __nv_bfloat16 hi[4], lo[4];
        #pragma unroll
        for (int i = 0; i < 4; i++) {
            hi[i] = __float2bfloat16_rn(q[i]);
            lo[i] = __float2bfloat16_rn(q[i] - __bfloat162float(hi[i]));
        }
        __nv_bfloat16* rowp = g_A + (size_t)t * ktotA;
        *reinterpret_cast<uint2*>(rowp + k)      = *reinterpret_cast<uint2*>(hi);
        *reinterpret_cast<uint2*>(rowp + IC + k) = *reinterpret_cast<uint2*>(lo);
    }
}

// ---------------------------------------------------------------------------
// Kernel 5: A outlier segments at 2*IC: gathered x columns hi/lo/hi + pad.
// ---------------------------------------------------------------------------
__global__ void gatherA_kernel(const float* __restrict__ x,
                               const int* __restrict__ cols,
                               int T, int IC, int NOUT, int ktotA) {
    int ntask = (ktotA - 2 * IC) - 2 * NOUT;
    size_t n = (size_t)T * ntask;
    for (size_t t0 = (size_t)blockIdx.x * blockDim.x + threadIdx.x; t0 < n;
         t0 += (size_t)gridDim.x * blockDim.x) {
        int t = (int)(t0 / ntask);
        int j = (int)(t0 % ntask);
        __nv_bfloat16* rowp = g_A + (size_t)t * ktotA + 2 * IC;
        if (j < NOUT) {
            int c = cols[j];
            float v = x[(size_t)t * IC + c];
            __nv_bfloat16 hi = __float2bfloat16_rn(v);
            __nv_bfloat16 lo = __float2bfloat16_rn(v - __bfloat162float(hi));
            rowp[j]            = hi;
            rowp[NOUT + j]     = lo;
            rowp[2 * NOUT + j] = hi;
        } else {
            rowp[2 * NOUT + j] = __float2bfloat16_rn(0.f);
        }
    }
}

// ---------------------------------------------------------------------------
// Kernel 6: GEMM. BM=BN=128, BK=64, 8 warps (2m x 4n of 64x32 tiles),
// 2-stage cp.async pipeline, 2 CTAs/SM, sign-reuse (one B tile vs A_hi+A_lo).
// Main chunks: dual-MMA against shared B tile; tail chunks: single.
// ---------------------------------------------------------------------------
#define BM 128
#define BN 128
#define BK 64
#define NSTAGE 2
#define TILE_BYTES   (128 * 128)                    // 16 KB per 128x64 bf16 tile
#define STAGE_BYTES  (3 * TILE_BYTES)               // A_hi + A_lo + B = 48 KB
#define GEMM_SMEM    (NSTAGE * STAGE_BYTES + 1024)  // 97 KB

__device__ __forceinline__ void load_tile(uint32_t dst, const char* src,
                                          int tid, size_t rowbytes) {
    #pragma unroll
    for (int i = 0; i < 4; i++) {
        int idx = tid + i * 256;
        int r = idx >> 3, c = idx & 7;
        CP_ASYNC16(dst + swz((uint32_t)(r * 128 + c * 16)),
                   src + (size_t)r * rowbytes + c * 16);
    }
}

// Prefetch chunk c into stage s. mainc = IC/BK main chunks; tail uses A slot 0.
__device__ __forceinline__ void prefetch_chunk(uint32_t sbase, int s, int c,
                                               int mainc,
                                               const char* Ag, const char* Bg,
                                               int IC, int tid,
                                               size_t rbA, size_t rbB) {
    uint32_t st = sbase + (uint32_t)s * STAGE_BYTES;
    if (c < mainc) {
        load_tile(st,                  Ag + (size_t)c * 128,                 tid, rbA);
        load_tile(st + TILE_BYTES,     Ag + (size_t)IC * 2 + (size_t)c * 128, tid, rbA);
        load_tile(st + 2 * TILE_BYTES, Bg + (size_t)c * 128,                 tid, rbB);
    } else {
        int tc = c - mainc;
        load_tile(st,                  Ag + (size_t)(2 * IC) * 2 + (size_t)tc * 128, tid, rbA);
        load_tile(st + 2 * TILE_BYTES, Bg + (size_t)IC * 2 + (size_t)tc * 128,      tid, rbB);
    }
}

__global__ __launch_bounds__(256, 2)
void gemm_mma(const float* __restrict__ bias, float* __restrict__ C,
              int T, int OC, int IC, int ktotA, int ktotB) {
    extern __shared__ char sm_raw[];
    uint32_t raw = smem_u32(sm_raw);
    uint32_t sbase = (raw + 1023u) & ~1023u;

    const int tid = threadIdx.x;
    const int lane = tid & 31, wid = tid >> 5;
    const int wm = (wid & 1) * 64;       // 2 warps in m
    const int wn = (wid >> 1) * 32;      // 4 warps in n

    const char* Ag = reinterpret_cast<const char*>(g_A + (size_t)(blockIdx.y * BM) * ktotA);
    const char* Bg = reinterpret_cast<const char*>(g_B + (size_t)(blockIdx.x * BN) * ktotB);
    const size_t rbA = (size_t)ktotA * 2;
    const size_t rbB = (size_t)ktotB * 2;

    float acc[4][4][4];
    #pragma unroll
    for (int mi = 0; mi < 4; mi++)
        #pragma unroll
        for (int nb = 0; nb < 4; nb++)
            #pragma unroll
            for (int e = 0; e < 4; e++) acc[mi][nb][e] = 0.f;

    const int mainc = IC / BK;                   // 64 dual chunks
    const int nch = mainc + (ktotA - 2 * IC) / BK;  // + tail chunks

    prefetch_chunk(sbase, 0, 0, mainc, Ag, Bg, IC, tid, rbA, rbB);
    CP_COMMIT();

    const int lrow = lane & 15;
    const int lkoff = (lane >> 4) * 16;
    const uint32_t arowoff = (uint32_t)((wm + lrow) * 128 + lkoff);
    const uint32_t browoff = (uint32_t)((wn + lrow) * 128 + lkoff);

    uint32_t afrag[4][4], bfrag[2][4];

    for (int ch = 0; ch < nch; ch++) {
        CP_WAIT(0);
        __syncthreads();

        if (ch + 1 < nch)
            prefetch_chunk(sbase, (ch + 1) & 1, ch + 1, mainc, Ag, Bg, IC,
                           tid, rbA, rbB);
        CP_COMMIT();

        uint32_t st = sbase + (uint32_t)(ch & 1) * STAGE_BYTES;
        uint32_t aHi = st, aLo = st + TILE_BYTES, bb = st + 2 * TILE_BYTES;
        bool dual = (ch < mainc);

        #pragma unroll
        for (int ks = 0; ks < 4; ks++) {
            uint32_t ko = (uint32_t)(ks * 32);
            // B fragments (shared by hi and lo passes)
            #pragma unroll
            for (int ni = 0; ni < 2; ni++)
                ldsm4(bfrag[ni], bb + swz(browoff + ko + (uint32_t)(ni * 2048)));
            // hi pass
            #pragma unroll
            for (int mi = 0; mi < 4; mi++)
                ldsm4(afrag[mi], aHi + swz(arowoff + ko + (uint32_t)(mi * 2048)));
            #pragma unroll
            for (int mi = 0; mi < 4; mi++) {
                #pragma unroll
                for (int ni = 0; ni < 2; ni++) {
                    mma16816(acc[mi][2 * ni],     afrag[mi], bfrag[ni][0], bfrag[ni][2]);
                    mma16816(acc[mi][2 * ni + 1], afrag[mi], bfrag[ni][1], bfrag[ni][3]);
                }
            }
            // lo pass (same B tile)
            if (dual) {
                #pragma unroll
                for (int mi = 0; mi < 4; mi++)
                    ldsm4(afrag[mi], aLo + swz(arowoff + ko + (uint32_t)(mi * 2048)));
                #pragma unroll
                for (int mi = 0; mi < 4; mi++) {
                    #pragma unroll
                    for (int ni = 0; ni < 2; ni++) {
                        mma16816(acc[mi][2 * ni],     afrag[mi], bfrag[ni][0], bfrag[ni][2]);
                        mma16816(acc[mi][2 * ni + 1], afrag[mi], bfrag[ni][1], bfrag[ni][3]);
                    }
                }
            }
        }
    }

    // Epilogue: C = acc * s_eff[col] + bias[col]
    int colb = blockIdx.x * BN + wn + (lane & 3) * 2;
    int rowb = blockIdx.y * BM + wm + (lane >> 2);
    #pragma unroll
    for (int nb = 0; nb < 4; nb++) {
        int col = colb + nb * 8;
        float s0 = g_seff[col],     s1 = g_seff[col + 1];
        float b0 = bias[col],       b1 = bias[col + 1];
        #pragma unroll
        for (int mi = 0; mi < 4; mi++) {
            int row = rowb + mi * 16;
            float2 v0 = make_float2(acc[mi][nb][0] * s0 + b0,
                                    acc[mi][nb][1] * s1 + b1);
            float2 v1 = make_float2(acc[mi][nb][2] * s0 + b0,
                                    acc[mi][nb][3] * s1 + b1);
            *reinterpret_cast<float2*>(C + (size_t)row * OC + col)       = v0;
            *reinterpret_cast<float2*>(C + (size_t)(row + 8) * OC + col) = v1;
        }
    }
}

// ---------------------------------------------------------------------------
// Launch
// ---------------------------------------------------------------------------
extern "C" void kernel_launch(void* const* d_in, const int* in_sizes, int n_in,
                              void* d_out, int out_size) {
    const float* x    = (const float*)d_in[0];
    const float* w    = (const float*)d_in[1];
    const float* bias = (const float*)d_in[2];
    const float* ow   = (const float*)d_in[3];
    const int*   cols = (const int*)d_in[4];

    int OC   = in_sizes[2];
    int IC   = in_sizes[1] / OC;
    int T    = in_sizes[0] / IC;
    int NOUT = in_sizes[3] / OC;
    int ktotA = (2 * IC + 3 * NOUT + 63) & ~63;
    int tail  = ktotA - 2 * IC;
    int ktotB = IC + tail;

    float* out = (float*)d_out;

    rowstats_kernel<<<OC, 256>>>(w, IC);

    {
        size_t n4 = (size_t)OC * IC / 4;
        int blocks = (int)((n4 + 255) / 256);
        if (blocks > 8192) blocks = 8192;
        prepB_kernel<<<blocks, 256>>>(w, OC, IC, ktotB);
    }
    {
        int ntask = tail - 2 * NOUT;
        size_t n = (size_t)OC * ntask;
        int blocks = (int)((n + 255) / 256);
        if (blocks > 4096) blocks = 4096;
        scatterB_kernel<<<blocks, 256>>>(w, ow, cols, OC, IC, NOUT, ktotB);
    }
    {
        size_t n4 = (size_t)T * IC / 4;
        int blocks = (int)((n4 + 255) / 256);
        if (blocks > 8192) blocks = 8192;
        prepA_kernel<<<blocks, 256>>>(x, T, IC, ktotA);
    }
    {
        int ntask = tail - 2 * NOUT;
        size_t n = (size_t)T * ntask;
        int blocks = (int)((n + 255) / 256);
        if (blocks > 4096) blocks = 4096;
        gatherA_kernel<<<blocks, 256>>>(x, cols, T, IC, NOUT, ktotA);
    }
    {
        static bool attr_set = false;
        if (!attr_set) {
            cudaFuncSetAttribute(gemm_mma,
                                 cudaFuncAttributeMaxDynamicSharedMemorySize,
                                 GEMM_SMEM);
            attr_set = true;
        }
        dim3 grid(OC / BN, T / BM);
        gemm_mma<<<grid, 256, GEMM_SMEM>>>(bias, out, T, OC, IC, ktotA, ktotB);
    }
}

// round 12
// speedup vs baseline: 6.4120x; 1.6594x over previous
#include <cuda_runtime.h>
#include <cuda_fp16.h>
#include <stdint.h>

// ---------------------------------------------------------------------------
// Dims: T=4096, IC=OC=4096, NOUT=204.
// Single-pass fp16 factorization:
//   wq[o][k] = scale[o] * sign[o][k]  with sign in {-1,0,+1} (exact in fp16)
//   outlier columns replaced; correction D'[o][j] = (ow - sign*scale)/s_eff
// A layout [T,  K]: [ x_f16(IC)   | x_gather_f16(NOUT) | pad0 ]
// B layout [OC, K]: [ sign_f16(IC)| D'_f16(NOUT)       | pad0 ]
// C[t][o] = (sum_k A[t][k]*B[o][k]) * s_eff[o] + bias[o]
// K = align64(IC + NOUT) = 4352. fp16 rel-err ~3e-4 << 1e-3 threshold.
// ---------------------------------------------------------------------------
#define MAX_OC 4096
#define MAX_IC 4096
#define MAXK   (MAX_IC + 256)   // 4352

__device__ __half g_A[(size_t)MAX_OC * MAXK];
__device__ __half g_B[(size_t)MAX_OC * MAXK];
__device__ float g_mean[MAX_OC];
__device__ float g_scale[MAX_OC];
__device__ float g_seff[MAX_OC];

// ---------------------------------------------------------------------------
// PTX helpers (sm_80-level: cp.async, ldmatrix, mma.sync)
// ---------------------------------------------------------------------------
__device__ __forceinline__ uint32_t smem_u32(const void* p) {
    uint32_t a;
    asm("{ .reg .u64 t; cvta.to.shared.u64 t, %1; cvt.u32.u64 %0, t; }"
        : "=r"(a) : "l"(p));
    return a;
}
#define CP_ASYNC16(dst, src) \
    asm volatile("cp.async.cg.shared.global [%0], [%1], 16;" :: "r"(dst), "l"(src))
#define CP_COMMIT() asm volatile("cp.async.commit_group;" ::: "memory")
#define CP_WAIT(n)  asm volatile("cp.async.wait_group %0;" :: "n"(n) : "memory")

__device__ __forceinline__ void ldsm4(uint32_t* r, uint32_t addr) {
    asm volatile("ldmatrix.sync.aligned.m8n8.x4.shared.b16 {%0,%1,%2,%3}, [%4];"
                 : "=r"(r[0]), "=r"(r[1]), "=r"(r[2]), "=r"(r[3]) : "r"(addr));
}
__device__ __forceinline__ void mma16816(float* d, const uint32_t* a,
                                         uint32_t b0, uint32_t b1) {
    asm volatile(
        "mma.sync.aligned.m16n8k16.row.col.f32.f16.f16.f32 "
        "{%0,%1,%2,%3}, {%4,%5,%6,%7}, {%8,%9}, {%0,%1,%2,%3};"
        : "+f"(d[0]), "+f"(d[1]), "+f"(d[2]), "+f"(d[3])
        : "r"(a[0]), "r"(a[1]), "r"(a[2]), "r"(a[3]), "r"(b0), "r"(b1));
}
__device__ __forceinline__ uint32_t swz(uint32_t off) {
    return off ^ ((off >> 3) & 0x70);
}

// ---------------------------------------------------------------------------
// Kernel 1: per-output-row mean / mean-abs-dev; s_eff = max(scale, tiny).
// ---------------------------------------------------------------------------
__global__ void rowstats_kernel(const float* __restrict__ w, int IC) {
    int o = blockIdx.x;
    const float* row = w + (size_t)o * IC;
    __shared__ float red[256];
    int tid = threadIdx.x;

    float s = 0.f;
    for (int i = tid; i < IC; i += 256) s += row[i];
    red[tid] = s;
    __syncthreads();
    #pragma unroll
    for (int off = 128; off > 0; off >>= 1) {
        if (tid < off) red[tid] += red[tid + off];
        __syncthreads();
    }
    float mean = red[0] / (float)IC;
    __syncthreads();

    float s2 = 0.f;
    for (int i = tid; i < IC; i += 256) s2 += fabsf(row[i] - mean);
    red[tid] = s2;
    __syncthreads();
    #pragma unroll
    for (int off = 128; off > 0; off >>= 1) {
        if (tid < off) red[tid] += red[tid + off];
        __syncthreads();
    }
    if (tid == 0) {
        float sc = red[0] / (float)IC;
        g_mean[o]  = mean;
        g_scale[o] = sc;
        g_seff[o]  = fmaxf(sc, 1e-20f);
    }
}

// ---------------------------------------------------------------------------
// Kernel 2: B main segment = sign matrix in fp16 (exact).
// ---------------------------------------------------------------------------
__global__ void prepB_kernel(const float* __restrict__ w, int OC, int IC, int ktot) {
    size_t n4 = (size_t)OC * IC / 4;
    int ic4 = IC / 4;
    for (size_t idx = (size_t)blockIdx.x * blockDim.x + threadIdx.x; idx < n4;
         idx += (size_t)gridDim.x * blockDim.x) {
        int o = (int)(idx / ic4);
        int k = (int)(idx % ic4) * 4;
        float mean = g_mean[o];
        float4 v = reinterpret_cast<const float4*>(w)[idx];
        __half sg[4];
        float a;
        a = v.x - mean; sg[0] = __float2half_rn((a > 0.f) ? 1.f : ((a < 0.f) ? -1.f : 0.f));
        a = v.y - mean; sg[1] = __float2half_rn((a > 0.f) ? 1.f : ((a < 0.f) ? -1.f : 0.f));
        a = v.z - mean; sg[2] = __float2half_rn((a > 0.f) ? 1.f : ((a < 0.f) ? -1.f : 0.f));
        a = v.w - mean; sg[3] = __float2half_rn((a > 0.f) ? 1.f : ((a < 0.f) ? -1.f : 0.f));
        __half* rowp = g_B + (size_t)o * ktot;
        *reinterpret_cast<uint2*>(rowp + k) = *reinterpret_cast<uint2*>(sg);
    }
}

// ---------------------------------------------------------------------------
// Kernel 3: B tail at offset IC: D' = (ow - sign*scale)/s_eff, then pad0.
// ---------------------------------------------------------------------------
__global__ void scatterB_kernel(const float* __restrict__ w,
                                const float* __restrict__ ow,
                                const int* __restrict__ cols,
                                int OC, int IC, int NOUT, int ktot) {
    int ntask = ktot - IC;  // NOUT + pad
    size_t n = (size_t)OC * ntask;
    for (size_t t = (size_t)blockIdx.x * blockDim.x + threadIdx.x; t < n;
         t += (size_t)gridDim.x * blockDim.x) {
        int o = (int)(t / ntask);
        int j = (int)(t % ntask);
        __half* rowp = g_B + (size_t)o * ktot + IC;
        if (j < NOUT) {
            int c = cols[j];
            float a = w[(size_t)o * IC + c] - g_mean[o];
            float sgn = (a > 0.f) ? 1.f : ((a < 0.f) ? -1.f : 0.f);
            float dp = (ow[(size_t)o * NOUT + j] - sgn * g_scale[o]) / g_seff[o];
            rowp[j] = __float2half_rn(dp);
        } else {
            rowp[j] = __float2half_rn(0.f);
        }
    }
}

// ---------------------------------------------------------------------------
// Kernel 4: A main segment: x -> fp16.
// ---------------------------------------------------------------------------
__global__ void prepA_kernel(const float* __restrict__ x, int T, int IC, int ktot) {
    size_t n4 = (size_t)T * IC / 4;
    int ic4 = IC / 4;
    for (size_t idx = (size_t)blockIdx.x * blockDim.x + threadIdx.x; idx < n4;
         idx += (size_t)gridDim.x * blockDim.x) {
        int t = (int)(idx / ic4);
        int k = (int)(idx % ic4) * 4;
        float4 v = reinterpret_cast<const float4*>(x)[idx];
        __half h[4];
        h[0] = __float2half_rn(v.x);
        h[1] = __float2half_rn(v.y);
        h[2] = __float2half_rn(v.z);
        h[3] = __float2half_rn(v.w);
        __half* rowp = g_A + (size_t)t * ktot;
        *reinterpret_cast<uint2*>(rowp + k) = *reinterpret_cast<uint2*>(h);
    }
}

// ---------------------------------------------------------------------------
// Kernel 5: A tail at offset IC: gathered outlier x columns fp16 + pad0.
// ---------------------------------------------------------------------------
__global__ void gatherA_kernel(const float* __restrict__ x,
                               const int* __restrict__ cols,
                               int T, int IC, int NOUT, int ktot) {
    int ntask = ktot - IC;
    size_t n = (size_t)T * ntask;
    for (size_t t0 = (size_t)blockIdx.x * blockDim.x + threadIdx.x; t0 < n;
         t0 += (size_t)gridDim.x * blockDim.x) {
        int t = (int)(t0 / ntask);
        int j = (int)(t0 % ntask);
        __half* rowp = g_A + (size_t)t * ktot + IC;
        if (j < NOUT) {
            int c = cols[j];
            rowp[j] = __float2half_rn(x[(size_t)t * IC + c]);
        } else {
            rowp[j] = __float2half_rn(0.f);
        }
    }
}

// ---------------------------------------------------------------------------
// Kernel 6: fp16 GEMM. BM=BN=128, BK=64, 8 warps (2m x 4n of 64x32 tiles),
// 3-stage cp.async pipeline, 2 CTAs/SM, epilogue scale+bias.
// ---------------------------------------------------------------------------
#define BM 128
#define BN 128
#define BK 64
#define NSTAGE 3
#define TILE_BYTES   (128 * 128)                    // 16 KB per 128x64 f16 tile
#define STAGE_BYTES  (2 * TILE_BYTES)               // A + B = 32 KB
#define GEMM_SMEM    (NSTAGE * STAGE_BYTES + 1024)  // 97 KB -> 2 CTAs/SM

__device__ __forceinline__ void load_tile(uint32_t dst, const char* src,
                                          int tid, size_t rowbytes) {
    #pragma unroll
    for (int i = 0; i < 4; i++) {
        int idx = tid + i * 256;
        int r = idx >> 3, c = idx & 7;
        CP_ASYNC16(dst + swz((uint32_t)(r * 128 + c * 16)),
                   src + (size_t)r * rowbytes + c * 16);
    }
}

__global__ __launch_bounds__(256, 2)
void gemm_mma(const float* __restrict__ bias, float* __restrict__ C,
              int T, int OC, int ktot) {
    extern __shared__ char sm_raw[];
    uint32_t raw = smem_u32(sm_raw);
    uint32_t sbase = (raw + 1023u) & ~1023u;

    const int tid = threadIdx.x;
    const int lane = tid & 31, wid = tid >> 5;
    const int wm = (wid & 1) * 64;       // 2 warps in m
    const int wn = (wid >> 1) * 32;      // 4 warps in n

    const char* Ag = reinterpret_cast<const char*>(g_A + (size_t)(blockIdx.y * BM) * ktot);
    const char* Bg = reinterpret_cast<const char*>(g_B + (size_t)(blockIdx.x * BN) * ktot);
    const size_t rowbytes = (size_t)ktot * 2;

    float acc[4][4][4];
    #pragma unroll
    for (int mi = 0; mi < 4; mi++)
        #pragma unroll
        for (int nb = 0; nb < 4; nb++)
            #pragma unroll
            for (int e = 0; e < 4; e++) acc[mi][nb][e] = 0.f;

    const int nch = ktot / BK;

    #pragma unroll
    for (int s = 0; s < NSTAGE - 1; s++) {
        uint32_t st = sbase + (uint32_t)s * STAGE_BYTES;
        load_tile(st,              Ag + (size_t)s * 128, tid, rowbytes);
        load_tile(st + TILE_BYTES, Bg + (size_t)s * 128, tid, rowbytes);
        CP_COMMIT();
    }

    const int lrow = lane & 15;
    const int lkoff = (lane >> 4) * 16;
    const uint32_t arowoff = (uint32_t)((wm + lrow) * 128 + lkoff);
    const uint32_t browoff = (uint32_t)((wn + lrow) * 128 + lkoff);

    uint32_t afrag[4][4], bfrag[2][4];

    for (int ch = 0; ch < nch; ch++) {
        CP_WAIT(NSTAGE - 2);
        __syncthreads();

        int pf = ch + NSTAGE - 1;
        if (pf < nch) {
            uint32_t st = sbase + (uint32_t)(pf % NSTAGE) * STAGE_BYTES;
            load_tile(st,              Ag + (size_t)pf * 128, tid, rowbytes);
            load_tile(st + TILE_BYTES, Bg + (size_t)pf * 128, tid, rowbytes);
        }
        CP_COMMIT();

        uint32_t st = sbase + (uint32_t)(ch % NSTAGE) * STAGE_BYTES;
        uint32_t ab = st, bb = st + TILE_BYTES;

        #pragma unroll
        for (int ks = 0; ks < 4; ks++) {
            uint32_t ko = (uint32_t)(ks * 32);
            #pragma unroll
            for (int ni = 0; ni < 2; ni++)
                ldsm4(bfrag[ni], bb + swz(browoff + ko + (uint32_t)(ni * 2048)));
            #pragma unroll
            for (int mi = 0; mi < 4; mi++)
                ldsm4(afrag[mi], ab + swz(arowoff + ko + (uint32_t)(mi * 2048)));
            #pragma unroll
            for (int mi = 0; mi < 4; mi++) {
                #pragma unroll
                for (int ni = 0; ni < 2; ni++) {
                    mma16816(acc[mi][2 * ni],     afrag[mi], bfrag[ni][0], bfrag[ni][2]);
                    mma16816(acc[mi][2 * ni + 1], afrag[mi], bfrag[ni][1], bfrag[ni][3]);
                }
            }
        }
    }

    // Epilogue: C = acc * s_eff[col] + bias[col]
    int colb = blockIdx.x * BN + wn + (lane & 3) * 2;
    int rowb = blockIdx.y * BM + wm + (lane >> 2);
    #pragma unroll
    for (int nb = 0; nb < 4; nb++) {
        int col = colb + nb * 8;
        float s0 = g_seff[col],     s1 = g_seff[col + 1];
        float b0 = bias[col],       b1 = bias[col + 1];
        #pragma unroll
        for (int mi = 0; mi < 4; mi++) {
            int row = rowb + mi * 16;
            float2 v0 = make_float2(acc[mi][nb][0] * s0 + b0,
                                    acc[mi][nb][1] * s1 + b1);
            float2 v1 = make_float2(acc[mi][nb][2] * s0 + b0,
                                    acc[mi][nb][3] * s1 + b1);
            *reinterpret_cast<float2*>(C + (size_t)row * OC + col)       = v0;
            *reinterpret_cast<float2*>(C + (size_t)(row + 8) * OC + col) = v1;
        }
    }
}

// ---------------------------------------------------------------------------
// Launch
// ---------------------------------------------------------------------------
extern "C" void kernel_launch(void* const* d_in, const int* in_sizes, int n_in,
                              void* d_out, int out_size) {
    const float* x    = (const float*)d_in[0];
    const float* w    = (const float*)d_in[1];
    const float* bias = (const float*)d_in[2];
    const float* ow   = (const float*)d_in[3];
    const int*   cols = (const int*)d_in[4];

    int OC   = in_sizes[2];
    int IC   = in_sizes[1] / OC;
    int T    = in_sizes[0] / IC;
    int NOUT = in_sizes[3] / OC;
    int ktot = (IC + NOUT + 63) & ~63;   // 4352

    float* out = (float*)d_out;

    rowstats_kernel<<<OC, 256>>>(w, IC);

    {
        size_t n4 = (size_t)OC * IC / 4;
        int blocks = (int)((n4 + 255) / 256);
        if (blocks > 8192) blocks = 8192;
        prepB_kernel<<<blocks, 256>>>(w, OC, IC, ktot);
    }
    {
        int ntask = ktot - IC;
        size_t n = (size_t)OC * ntask;
        int blocks = (int)((n + 255) / 256);
        if (blocks > 4096) blocks = 4096;
        scatterB_kernel<<<blocks, 256>>>(w, ow, cols, OC, IC, NOUT, ktot);
    }
    {
        size_t n4 = (size_t)T * IC / 4;
        int blocks = (int)((n4 + 255) / 256);
        if (blocks > 8192) blocks = 8192;
        prepA_kernel<<<blocks, 256>>>(x, T, IC, ktot);
    }
    {
        int ntask = ktot - IC;
        size_t n = (size_t)T * ntask;
        int blocks = (int)((n + 255) / 256);
        if (blocks > 4096) blocks = 4096;
        gatherA_kernel<<<blocks, 256>>>(x, cols, T, IC, NOUT, ktot);
    }
    {
        static bool attr_set = false;
        if (!attr_set) {
            cudaFuncSetAttribute(gemm_mma,
                                 cudaFuncAttributeMaxDynamicSharedMemorySize,
                                 GEMM_SMEM);
            attr_set = true;
        }
        dim3 grid(OC / BN, T / BM);
        gemm_mma<<<grid, 256, GEMM_SMEM>>>(bias, out, T, OC, ktot);
    }
}

// round 13
// speedup vs baseline: 6.5705x; 1.0247x over previous
#include <cuda_runtime.h>
#include <cuda_fp16.h>
#include <stdint.h>

// ---------------------------------------------------------------------------
// Dims: T=4096, IC=OC=4096, NOUT=204.
// Single-pass fp16 factorization:
//   wq[o][k] = scale[o] * sign[o][k]  with sign in {-1,0,+1} (exact in fp16)
//   outlier columns replaced; correction D'[o][j] = (ow - sign*scale)/s_eff
// A layout [T,  K]: [ x_f16(IC)   | x_gather_f16(NOUT) | pad0 ]
// B layout [OC, K]: [ sign_f16(IC)| D'_f16(NOUT)       | pad0 ]
// C[t][o] = (sum_k A[t][k]*B[o][k]) * s_eff[o] + bias[o]
// K = align64(IC + NOUT) = 4352. fp16 rel-err ~2e-4 << 1e-3 threshold.
// ---------------------------------------------------------------------------
#define MAX_OC 4096
#define MAX_IC 4096
#define MAXK   (MAX_IC + 256)   // 4352

__device__ __half g_A[(size_t)MAX_OC * MAXK];
__device__ __half g_B[(size_t)MAX_OC * MAXK];
__device__ float g_mean[MAX_OC];
__device__ float g_scale[MAX_OC];
__device__ float g_seff[MAX_OC];

// ---------------------------------------------------------------------------
// PTX helpers (sm_80-level: cp.async, ldmatrix, mma.sync)
// ---------------------------------------------------------------------------
__device__ __forceinline__ uint32_t smem_u32(const void* p) {
    uint32_t a;
    asm("{ .reg .u64 t; cvta.to.shared.u64 t, %1; cvt.u32.u64 %0, t; }"
        : "=r"(a) : "l"(p));
    return a;
}
#define CP_ASYNC16(dst, src) \
    asm volatile("cp.async.cg.shared.global [%0], [%1], 16;" :: "r"(dst), "l"(src))
#define CP_COMMIT() asm volatile("cp.async.commit_group;" ::: "memory")
#define CP_WAIT(n)  asm volatile("cp.async.wait_group %0;" :: "n"(n) : "memory")

__device__ __forceinline__ void ldsm4(uint32_t* r, uint32_t addr) {
    asm volatile("ldmatrix.sync.aligned.m8n8.x4.shared.b16 {%0,%1,%2,%3}, [%4];"
                 : "=r"(r[0]), "=r"(r[1]), "=r"(r[2]), "=r"(r[3]) : "r"(addr));
}
__device__ __forceinline__ void mma16816(float* d, const uint32_t* a,
                                         uint32_t b0, uint32_t b1) {
    asm volatile(
        "mma.sync.aligned.m16n8k16.row.col.f32.f16.f16.f32 "
        "{%0,%1,%2,%3}, {%4,%5,%6,%7}, {%8,%9}, {%0,%1,%2,%3};"
        : "+f"(d[0]), "+f"(d[1]), "+f"(d[2]), "+f"(d[3])
        : "r"(a[0]), "r"(a[1]), "r"(a[2]), "r"(a[3]), "r"(b0), "r"(b1));
}
__device__ __forceinline__ uint32_t swz(uint32_t off) {
    return off ^ ((off >> 3) & 0x70);
}

// ---------------------------------------------------------------------------
// Kernel 1: per-output-row mean / mean-abs-dev; s_eff = max(scale, tiny).
// ---------------------------------------------------------------------------
__global__ void rowstats_kernel(const float* __restrict__ w, int IC) {
    int o = blockIdx.x;
    const float* row = w + (size_t)o * IC;
    __shared__ float red[256];
    int tid = threadIdx.x;

    float s = 0.f;
    for (int i = tid; i < IC; i += 256) s += row[i];
    red[tid] = s;
    __syncthreads();
    #pragma unroll
    for (int off = 128; off > 0; off >>= 1) {
        if (tid < off) red[tid] += red[tid + off];
        __syncthreads();
    }
    float mean = red[0] / (float)IC;
    __syncthreads();

    float s2 = 0.f;
    for (int i = tid; i < IC; i += 256) s2 += fabsf(row[i] - mean);
    red[tid] = s2;
    __syncthreads();
    #pragma unroll
    for (int off = 128; off > 0; off >>= 1) {
        if (tid < off) red[tid] += red[tid + off];
        __syncthreads();
    }
    if (tid == 0) {
        float sc = red[0] / (float)IC;
        g_mean[o]  = mean;
        g_scale[o] = sc;
        g_seff[o]  = fmaxf(sc, 1e-20f);
    }
}

// ---------------------------------------------------------------------------
// Kernel 2: B main segment = sign matrix in fp16. 2D grid, no div/mod.
// grid (IC/1024, OC), block 256; thread handles one float4 (4 elems).
// ---------------------------------------------------------------------------
__global__ void prepB_kernel(const float* __restrict__ w, int IC, int ktot) {
    int o  = blockIdx.y;
    int k4 = blockIdx.x * 256 + threadIdx.x;   // float4 index within row
    float mean = g_mean[o];
    float4 v = reinterpret_cast<const float4*>(w + (size_t)o * IC)[k4];
    __half sg[4];
    float a;
    a = v.x - mean; sg[0] = __float2half_rn((a > 0.f) ? 1.f : ((a < 0.f) ? -1.f : 0.f));
    a = v.y - mean; sg[1] = __float2half_rn((a > 0.f) ? 1.f : ((a < 0.f) ? -1.f : 0.f));
    a = v.z - mean; sg[2] = __float2half_rn((a > 0.f) ? 1.f : ((a < 0.f) ? -1.f : 0.f));
    a = v.w - mean; sg[3] = __float2half_rn((a > 0.f) ? 1.f : ((a < 0.f) ? -1.f : 0.f));
    *reinterpret_cast<uint2*>(g_B + (size_t)o * ktot + k4 * 4) =
        *reinterpret_cast<uint2*>(sg);
}

// ---------------------------------------------------------------------------
// Kernel 3: B tail at offset IC: D' = (ow - sign*scale)/s_eff, then pad0.
// grid (1, OC), block = ntask (<=256).
// ---------------------------------------------------------------------------
__global__ void scatterB_kernel(const float* __restrict__ w,
                                const float* __restrict__ ow,
                                const int* __restrict__ cols,
                                int IC, int NOUT, int ktot) {
    int o = blockIdx.y;
    int j = threadIdx.x;
    int ntask = ktot - IC;
    if (j >= ntask) return;
    __half* rowp = g_B + (size_t)o * ktot + IC;
    if (j < NOUT) {
        int c = cols[j];
        float a = w[(size_t)o * IC + c] - g_mean[o];
        float sgn = (a > 0.f) ? 1.f : ((a < 0.f) ? -1.f : 0.f);
        float dp = (ow[(size_t)o * NOUT + j] - sgn * g_scale[o]) / g_seff[o];
        rowp[j] = __float2half_rn(dp);
    } else {
        rowp[j] = __float2half_rn(0.f);
    }
}

// ---------------------------------------------------------------------------
// Kernel 4: A main segment: x -> fp16. 2D grid, no div/mod.
// ---------------------------------------------------------------------------
__global__ void prepA_kernel(const float* __restrict__ x, int IC, int ktot) {
    int t  = blockIdx.y;
    int k4 = blockIdx.x * 256 + threadIdx.x;
    float4 v = reinterpret_cast<const float4*>(x + (size_t)t * IC)[k4];
    __half h[4];
    h[0] = __float2half_rn(v.x);
    h[1] = __float2half_rn(v.y);
    h[2] = __float2half_rn(v.z);
    h[3] = __float2half_rn(v.w);
    *reinterpret_cast<uint2*>(g_A + (size_t)t * ktot + k4 * 4) =
        *reinterpret_cast<uint2*>(h);
}

// ---------------------------------------------------------------------------
// Kernel 5: A tail at offset IC: gathered outlier x columns fp16 + pad0.
// grid (1, T), block = ntask (<=256).
// ---------------------------------------------------------------------------
__global__ void gatherA_kernel(const float* __restrict__ x,
                               const int* __restrict__ cols,
                               int IC, int NOUT, int ktot) {
    int t = blockIdx.y;
    int j = threadIdx.x;
    int ntask = ktot - IC;
    if (j >= ntask) return;
    __half* rowp = g_A + (size_t)t * ktot + IC;
    if (j < NOUT) {
        int c = cols[j];
        rowp[j] = __float2half_rn(x[(size_t)t * IC + c]);
    } else {
        rowp[j] = __float2half_rn(0.f);
    }
}

// ---------------------------------------------------------------------------
// Kernel 6: fp16 GEMM. BM=BN=128, BK=64, 8 warps (2m x 4n of 64x32 tiles),
// 3-stage cp.async pipeline, 2 CTAs/SM, ks-level register double-buffered
// fragments, epilogue scale+bias.
// ---------------------------------------------------------------------------
#define BM 128
#define BN 128
#define BK 64
#define NSTAGE 3
#define TILE_BYTES   (128 * 128)                    // 16 KB per 128x64 f16 tile
#define STAGE_BYTES  (2 * TILE_BYTES)               // A + B = 32 KB
#define GEMM_SMEM    (NSTAGE * STAGE_BYTES + 1024)  // 97 KB -> 2 CTAs/SM

__device__ __forceinline__ void load_tile(uint32_t dst, const char* src,
                                          int tid, size_t rowbytes) {
    #pragma unroll
    for (int i = 0; i < 4; i++) {
        int idx = tid + i * 256;
        int r = idx >> 3, c = idx & 7;
        CP_ASYNC16(dst + swz((uint32_t)(r * 128 + c * 16)),
                   src + (size_t)r * rowbytes + c * 16);
    }
}

__global__ __launch_bounds__(256, 2)
void gemm_mma(const float* __restrict__ bias, float* __restrict__ C,
              int T, int OC, int ktot) {
    extern __shared__ char sm_raw[];
    uint32_t raw = smem_u32(sm_raw);
    uint32_t sbase = (raw + 1023u) & ~1023u;

    const int tid = threadIdx.x;
    const int lane = tid & 31, wid = tid >> 5;
    const int wm = (wid & 1) * 64;       // 2 warps in m
    const int wn = (wid >> 1) * 32;      // 4 warps in n

    const char* Ag = reinterpret_cast<const char*>(g_A + (size_t)(blockIdx.y * BM) * ktot);
    const char* Bg = reinterpret_cast<const char*>(g_B + (size_t)(blockIdx.x * BN) * ktot);
    const size_t rowbytes = (size_t)ktot * 2;

    float acc[4][4][4];
    #pragma unroll
    for (int mi = 0; mi < 4; mi++)
        #pragma unroll
        for (int nb = 0; nb < 4; nb++)
            #pragma unroll
            for (int e = 0; e < 4; e++) acc[mi][nb][e] = 0.f;

    const int nch = ktot / BK;

    #pragma unroll
    for (int s = 0; s < NSTAGE - 1; s++) {
        uint32_t st = sbase + (uint32_t)s * STAGE_BYTES;
        load_tile(st,              Ag + (size_t)s * 128, tid, rowbytes);
        load_tile(st + TILE_BYTES, Bg + (size_t)s * 128, tid, rowbytes);
        CP_COMMIT();
    }

    const int lrow = lane & 15;
    const int lkoff = (lane >> 4) * 16;
    const uint32_t arowoff = (uint32_t)((wm + lrow) * 128 + lkoff);
    const uint32_t browoff = (uint32_t)((wn + lrow) * 128 + lkoff);

    uint32_t afrag[2][4][4], bfrag[2][2][4];

    for (int ch = 0; ch < nch; ch++) {
        CP_WAIT(NSTAGE - 2);
        __syncthreads();

        int pf = ch + NSTAGE - 1;
        if (pf < nch) {
            uint32_t st = sbase + (uint32_t)(pf % NSTAGE) * STAGE_BYTES;
            load_tile(st,              Ag + (size_t)pf * 128, tid, rowbytes);
            load_tile(st + TILE_BYTES, Bg + (size_t)pf * 128, tid, rowbytes);
        }
        CP_COMMIT();

        uint32_t st = sbase + (uint32_t)(ch % NSTAGE) * STAGE_BYTES;
        uint32_t ab = st, bb = st + TILE_BYTES;

        // Preload ks=0 fragments into buffer 0.
        #pragma unroll
        for (int ni = 0; ni < 2; ni++)
            ldsm4(bfrag[0][ni], bb + swz(browoff + (uint32_t)(ni * 2048)));
        #pragma unroll
        for (int mi = 0; mi < 4; mi++)
            ldsm4(afrag[0][mi], ab + swz(arowoff + (uint32_t)(mi * 2048)));

        #pragma unroll
        for (int ks = 0; ks < 4; ks++) {
            int cur = ks & 1;
            int nxt = cur ^ 1;
            if (ks < 3) {
                uint32_t ko = (uint32_t)((ks + 1) * 32);
                #pragma unroll
                for (int ni = 0; ni < 2; ni++)
                    ldsm4(bfrag[nxt][ni],
                          bb + swz(browoff + ko + (uint32_t)(ni * 2048)));
                #pragma unroll
                for (int mi = 0; mi < 4; mi++)
                    ldsm4(afrag[nxt][mi],
                          ab + swz(arowoff + ko + (uint32_t)(mi * 2048)));
            }
            #pragma unroll
            for (int mi = 0; mi < 4; mi++) {
                #pragma unroll
                for (int ni = 0; ni < 2; ni++) {
                    mma16816(acc[mi][2 * ni],     afrag[cur][mi],
                             bfrag[cur][ni][0], bfrag[cur][ni][2]);
                    mma16816(acc[mi][2 * ni + 1], afrag[cur][mi],
                             bfrag[cur][ni][1], bfrag[cur][ni][3]);
                }
            }
        }
    }

    // Epilogue: C = acc * s_eff[col] + bias[col]
    int colb = blockIdx.x * BN + wn + (lane & 3) * 2;
    int rowb = blockIdx.y * BM + wm + (lane >> 2);
    #pragma unroll
    for (int nb = 0; nb < 4; nb++) {
        int col = colb + nb * 8;
        float s0 = g_seff[col],     s1 = g_seff[col + 1];
        float b0 = bias[col],       b1 = bias[col + 1];
        #pragma unroll
        for (int mi = 0; mi < 4; mi++) {
            int row = rowb + mi * 16;
            float2 v0 = make_float2(acc[mi][nb][0] * s0 + b0,
                                    acc[mi][nb][1] * s1 + b1);
            float2 v1 = make_float2(acc[mi][nb][2] * s0 + b0,
                                    acc[mi][nb][3] * s1 + b1);
            *reinterpret_cast<float2*>(C + (size_t)row * OC + col)       = v0;
            *reinterpret_cast<float2*>(C + (size_t)(row + 8) * OC + col) = v1;
        }
    }
}

// ---------------------------------------------------------------------------
// Launch
// ---------------------------------------------------------------------------
extern "C" void kernel_launch(void* const* d_in, const int* in_sizes, int n_in,
                              void* d_out, int out_size) {
    const float* x    = (const float*)d_in[0];
    const float* w    = (const float*)d_in[1];
    const float* bias = (const float*)d_in[2];
    const float* ow   = (const float*)d_in[3];
    const int*   cols = (const int*)d_in[4];

    int OC   = in_sizes[2];
    int IC   = in_sizes[1] / OC;
    int T    = in_sizes[0] / IC;
    int NOUT = in_sizes[3] / OC;
    int ktot = (IC + NOUT + 63) & ~63;   // 4352
    int ntask = ktot - IC;               // 256

    float* out = (float*)d_out;

    rowstats_kernel<<<OC, 256>>>(w, IC);

    {
        dim3 grid(IC / 1024, OC);
        prepB_kernel<<<grid, 256>>>(w, IC, ktot);
    }
    {
        dim3 grid(1, OC);
        scatterB_kernel<<<grid, ntask>>>(w, ow, cols, IC, NOUT, ktot);
    }
    {
        dim3 grid(IC / 1024, T);
        prepA_kernel<<<grid, 256>>>(x, IC, ktot);
    }
    {
        dim3 grid(1, T);
        gatherA_kernel<<<grid, ntask>>>(x, cols, IC, NOUT, ktot);
    }
    {
        static bool attr_set = false;
        if (!attr_set) {
            cudaFuncSetAttribute(gemm_mma,
                                 cudaFuncAttributeMaxDynamicSharedMemorySize,
                                 GEMM_SMEM);
            attr_set = true;
        }
        dim3 grid(OC / BN, T / BM);
        gemm_mma<<<grid, 256, GEMM_SMEM>>>(bias, out, T, OC, ktot);
    }
}